// round 14
// baseline (speedup 1.0000x reference)
#include <cuda_runtime.h>
#include <cuda_fp16.h>
#include <cstdint>

#define B_   64
#define T_   512
#define H_   128
#define E_   300
#define C_   20
#define G4_  512
#define BT_  (B_ * T_)          // 32768
#define KP_  320                // K padded for fp16 tables
#define GP_  40                 // GEMM smem pitch in halves

// -------- scratch (static device globals; no runtime allocation) -----------
__device__ __align__(16) __half g_xembh[(unsigned)BT_ * KP_];  // 21 MB
__device__ __align__(16) __half g_Wh[2u * G4_ * KP_];          // 0.66 MB
__device__ __align__(16) __half g_xq[2u * BT_ * G4_];          // 64 MB, gate-interleaved
__device__ __align__(16) float g_h [(unsigned)BT_ * 2 * H_];   // 32 MB
__device__ __align__(16) float g_eexp[(unsigned)BT_ * C_];
__device__ float g_em0[BT_];
__device__ float g_res[B_];
__device__ float g_bias[2 * G4_];

// ----------------------------- math helpers --------------------------------
__device__ __forceinline__ float fast_sigmoid(float x) {
    return __fdividef(1.0f, 1.0f + __expf(-x));
}
__device__ __forceinline__ float fast_tanh(float x) {
    float ax = fabsf(x);
    float e  = __expf(-2.0f * ax);
    float t  = __fdividef(1.0f - e, 1.0f + e);
    return copysignf(t, x);
}
__device__ __forceinline__ int load_mask(const void* m, long idx, int isbyte) {
    return isbyte ? (int)((const unsigned char*)m)[idx] : ((const int*)m)[idx];
}
__device__ __forceinline__ void ldsm4(unsigned& r0, unsigned& r1,
                                      unsigned& r2, unsigned& r3,
                                      unsigned addr) {
    asm volatile("ldmatrix.sync.aligned.m8n8.x4.shared.b16 {%0,%1,%2,%3}, [%4];"
                 : "=r"(r0), "=r"(r1), "=r"(r2), "=r"(r3) : "r"(addr));
}
__device__ __forceinline__ void mma16816(float* c,
                                         unsigned a0, unsigned a1,
                                         unsigned a2, unsigned a3,
                                         unsigned b0, unsigned b1) {
    asm volatile("mma.sync.aligned.m16n8k16.row.col.f32.f16.f16.f32 "
                 "{%0,%1,%2,%3}, {%4,%5,%6,%7}, {%8,%9}, {%0,%1,%2,%3};"
                 : "+f"(c[0]), "+f"(c[1]), "+f"(c[2]), "+f"(c[3])
                 : "r"(a0), "r"(a1), "r"(a2), "r"(a3), "r"(b0), "r"(b1));
}
__device__ __forceinline__ void cp16(unsigned dst, const void* src) {
    asm volatile("cp.async.cg.shared.global [%0], [%1], 16;"
                 :: "r"(dst), "l"(src));
}
__device__ __forceinline__ void cp_commit() {
    asm volatile("cp.async.commit_group;");
}
template <int N>
__device__ __forceinline__ void cp_wait() {
    asm volatile("cp.async.wait_group %0;" :: "n"(N));
}

// ==========================================================================
// Kernel 0: per-token fp16 embedding gather-convert + W_ih convert.
// ==========================================================================
__global__ void __launch_bounds__(256) k_cvt(
    const int*   __restrict__ x,
    const float* __restrict__ emb,
    const float* __restrict__ Wf, const float* __restrict__ Wb)
{
    const long NE = (long)BT_ * (KP_ / 2);
    const long NW = (long)2 * G4_ * (KP_ / 2);
    long i = (long)blockIdx.x * 256 + threadIdx.x;
    if (i < NE) {
        long bt  = i / (KP_ / 2);
        int  col = 2 * (int)(i % (KP_ / 2));
        __half2 v;
        if (col < 300) {
            const float* s = emb + (long)x[bt] * 300 + col;
            v = __floats2half2_rn(s[0], s[1]);
        } else v = __floats2half2_rn(0.f, 0.f);
        ((__half2*)g_xembh)[i] = v;
    } else if (i < NE + NW) {
        long j   = i - NE;
        long row = j / (KP_ / 2);
        int  col = 2 * (int)(j % (KP_ / 2));
        const float* W = (row < G4_) ? Wf : Wb;
        long r = (row < G4_) ? row : row - G4_;
        __half2 v;
        if (col < 300) {
            const float* s = W + r * 300 + col;
            v = __floats2half2_rn(s[0], s[1]);
        } else v = __floats2half2_rn(0.f, 0.f);
        ((__half2*)g_Wh)[j] = v;
    }
}

__global__ void k_bias(const float* __restrict__ bif, const float* __restrict__ bhf,
                       const float* __restrict__ bib, const float* __restrict__ bhb)
{
    int i = blockIdx.x * 256 + threadIdx.x;
    if (i < G4_)          g_bias[i] = bif[i] + bhf[i];
    else if (i < 2 * G4_) g_bias[i] = bib[i - G4_] + bhb[i - G4_];
}

// ==========================================================================
// Kernel 1: input GEMM — HMMA + cp.async 3-stage; sequential A.
//   Epilogue writes GATE-INTERLEAVED fp16: g_xq[...][h*4 + gate].
// ==========================================================================
__global__ void __launch_bounds__(256, 2) k_input_gemm()
{
    extern __shared__ __align__(16) char gsm[];
    __half* sA = (__half*)gsm;
    __half* sB = (__half*)(gsm + 3 * 5120 * 2);

    const int tid   = threadIdx.x;
    const int lane  = tid & 31;
    const int wid   = tid >> 5;
    const int wm    = wid >> 1;
    const int wn    = wid & 1;
    const int m0    = blockIdx.y * 128;
    const int n0g   = blockIdx.x * 128;
    const int dir   = n0g >> 9;
    const int gbase = n0g & 511;

    const int  lrow = tid >> 1;
    const int  hoff = (tid & 1) * 16;
    const __half* srcA = g_xembh + (long)(m0 + lrow) * KP_ + hoff;
    const __half* srcB = g_Wh + ((long)dir * G4_ + gbase + lrow) * KP_ + hoff;
    const unsigned sAb = (unsigned)__cvta_generic_to_shared(sA);
    const unsigned sBb = (unsigned)__cvta_generic_to_shared(sB);
    const unsigned dA0 = sAb + (unsigned)((lrow * GP_ + hoff) * 2);
    const unsigned dB0 = sBb + (unsigned)((lrow * GP_ + hoff) * 2);

    float cacc[2][8][4];
#pragma unroll
    for (int mt = 0; mt < 2; mt++)
#pragma unroll
        for (int nt = 0; nt < 8; nt++)
#pragma unroll
            for (int r = 0; r < 4; r++) cacc[mt][nt][r] = 0.0f;

    auto ISSUE = [&](int s) {
        const unsigned bo = (unsigned)((s % 3) * 5120 * 2);
        const __half* a = srcA + s * 32;
        const __half* b = srcB + s * 32;
        cp16(dA0 + bo,      a);
        cp16(dA0 + bo + 16, a + 8);
        cp16(dB0 + bo,      b);
        cp16(dB0 + bo + 16, b + 8);
        cp_commit();
    };

    ISSUE(0); ISSUE(1);

    for (int ks = 0; ks < 10; ks++) {
        cp_wait<1>();
        __syncthreads();
        if (ks < 8) ISSUE(ks + 2);

        const unsigned bo = (unsigned)((ks % 3) * 5120 * 2);
        const unsigned bA = sAb + bo;
        const unsigned bB = sBb + bo;
#pragma unroll
        for (int ks2 = 0; ks2 < 2; ks2++) {
            const int k0 = ks2 * 16;
            unsigned a[2][4];
#pragma unroll
            for (int mt = 0; mt < 2; mt++) {
                int row = wm * 32 + mt * 16 + (lane & 15);
                unsigned ad = bA + (unsigned)((row * GP_ + k0 + (lane >> 4) * 8) * 2);
                ldsm4(a[mt][0], a[mt][1], a[mt][2], a[mt][3], ad);
            }
            unsigned b[8][2];
#pragma unroll
            for (int ntp = 0; ntp < 4; ntp++) {
                int nr = wn * 64 + ntp * 16 + (lane & 7) + (lane >> 4) * 8;
                unsigned ad = bB + (unsigned)((nr * GP_ + k0 + ((lane >> 3) & 1) * 8) * 2);
                unsigned r0, r1, r2, r3;
                ldsm4(r0, r1, r2, r3, ad);
                b[2*ntp][0] = r0;  b[2*ntp][1] = r1;
                b[2*ntp+1][0] = r2; b[2*ntp+1][1] = r3;
            }
#pragma unroll
            for (int mt = 0; mt < 2; mt++)
#pragma unroll
                for (int nt = 0; nt < 8; nt++)
                    mma16816(cacc[mt][nt], a[mt][0], a[mt][1], a[mt][2], a[mt][3],
                             b[nt][0], b[nt][1]);
        }
    }

    // epilogue: bias + gate-interleaved fp16 stores (pos = h*4 + gate_type)
    const int qr = lane >> 2;
    const int qc = (lane & 3) * 2;
    __half* outbase = g_xq + (long)dir * BT_ * G4_;
    const float* bsum = g_bias + dir * G4_;
#pragma unroll
    for (int nt = 0; nt < 8; nt++) {
        int gc = gbase + wn * 64 + nt * 8 + qc;        // gate index 0..511
        int p0 = (gc & 127) * 4 + (gc >> 7);           // interleaved pos
        int p1 = ((gc + 1) & 127) * 4 + ((gc + 1) >> 7);
        float bx = bsum[gc];
        float by = bsum[gc + 1];
#pragma unroll
        for (int mt = 0; mt < 2; mt++) {
            long gm = m0 + wm * 32 + mt * 16 + qr;
            __half* o0 = outbase + gm * G4_;
            __half* o1 = outbase + (gm + 8) * G4_;
            o0[p0] = __float2half(cacc[mt][nt][0] + bx);
            o0[p1] = __float2half(cacc[mt][nt][1] + by);
            o1[p0] = __float2half(cacc[mt][nt][2] + bx);
            o1[p1] = __float2half(cacc[mt][nt][3] + by);
        }
    }
}

// ==========================================================================
// Kernel 2: LSTM v4r2 — tensor-core recurrence; gate-interleaved xw with
//   ONE LDG.64 per cell thread per step and depth-2 prefetch.
// ==========================================================================
__global__ void __launch_bounds__(512) k_lstm(
    const float* __restrict__ Whf, const float* __restrict__ Whb)
{
    __shared__ __half sh16[2][128];     // h per batch (fp16, k-contiguous)
    __shared__ float  sg[2][512];       // gates per batch

    const int tid  = threadIdx.x;
    const int lane = tid & 31;
    const int wid  = tid >> 5;          // 0..15
    const int dir  = blockIdx.x >> 5;
    const int bg   = blockIdx.x & 31;   // batches 2bg, 2bg+1
    const float* Wh = dir ? Whb : Whf;

    // A-fragment preload (rows = gates, cols = k), once.
    unsigned afr[2][8][4];
    {
        const int g = lane >> 2, t4 = lane & 3;
#pragma unroll
        for (int mt = 0; mt < 2; mt++) {
            int r0 = wid * 32 + mt * 16 + g;
#pragma unroll
            for (int ks = 0; ks < 8; ks++) {
                int k0 = ks * 16 + 2 * t4;
                float2 w00 = *(const float2*)(Wh + (long)r0 * 128 + k0);
                float2 w10 = *(const float2*)(Wh + (long)(r0 + 8) * 128 + k0);
                float2 w01 = *(const float2*)(Wh + (long)r0 * 128 + k0 + 8);
                float2 w11 = *(const float2*)(Wh + (long)(r0 + 8) * 128 + k0 + 8);
                __half2 h00 = __floats2half2_rn(w00.x, w00.y);
                __half2 h10 = __floats2half2_rn(w10.x, w10.y);
                __half2 h01 = __floats2half2_rn(w01.x, w01.y);
                __half2 h11 = __floats2half2_rn(w11.x, w11.y);
                afr[mt][ks][0] = *(unsigned*)&h00;
                afr[mt][ks][1] = *(unsigned*)&h10;
                afr[mt][ks][2] = *(unsigned*)&h01;
                afr[mt][ks][3] = *(unsigned*)&h11;
            }
        }
    }

    if (tid < 256) {
        int n = tid >> 7, i = tid & 127;
        sh16[n][i] = __float2half(0.0f);
    }
    float cst = 0.0f;
    __syncthreads();

    const int cn = tid >> 7;            // cell-update batch (tid<256)
    const int ci = tid & 127;           // cell-update h index
    const long xwrow0 = ((long)dir * BT_ + (long)(2 * bg + cn) * T_) * G4_;
    const uint2* xqp = (const uint2*)(g_xq + xwrow0) + ci;   // stride 128 uint2/t
    float* hout = g_h + ((long)(2 * bg + cn) * T_) * (2 * H_) + dir * H_ + ci;

    int t  = dir ? (T_ - 1) : 0;
    const int dt = dir ? -1 : 1;

    // depth-2 prefetch of gate-interleaved xw (one LDG.64 per step)
    uint2 xq[2];
    if (tid < 256) {
        xq[0] = xqp[(long)t * 128];
        if (T_ > 1) xq[1] = xqp[(long)(t + dt) * 128];
    }

    const int bn = lane >> 2;           // B-frag column (batch if < 2)
    const int bk = (lane & 3) * 2;      // B-frag k base

    for (int s = 0; s < T_; s++, t += dt) {
        // matvec, split even/odd-ks chains (HMMA dependency depth 4)
        float c0e[4] = {0,0,0,0}, c0o[4] = {0,0,0,0};
        float c1e[4] = {0,0,0,0}, c1o[4] = {0,0,0,0};
#pragma unroll
        for (int ks = 0; ks < 8; ks += 2) {
            unsigned b0 = 0, b1 = 0, b2 = 0, b3 = 0;
            if (bn < 2) {
                b0 = *(const unsigned*)&sh16[bn][ks * 16 + bk];
                b1 = *(const unsigned*)&sh16[bn][ks * 16 + bk + 8];
                b2 = *(const unsigned*)&sh16[bn][ks * 16 + 16 + bk];
                b3 = *(const unsigned*)&sh16[bn][ks * 16 + 16 + bk + 8];
            }
            mma16816(c0e, afr[0][ks][0], afr[0][ks][1], afr[0][ks][2],
                     afr[0][ks][3], b0, b1);
            mma16816(c1e, afr[1][ks][0], afr[1][ks][1], afr[1][ks][2],
                     afr[1][ks][3], b0, b1);
            mma16816(c0o, afr[0][ks+1][0], afr[0][ks+1][1], afr[0][ks+1][2],
                     afr[0][ks+1][3], b2, b3);
            mma16816(c1o, afr[1][ks+1][0], afr[1][ks+1][1], afr[1][ks+1][2],
                     afr[1][ks+1][3], b2, b3);
        }
        if ((lane & 3) == 0) {
            int r0 = wid * 32 + (lane >> 2);
            sg[0][r0]      = c0e[0] + c0o[0];  sg[1][r0]      = c0e[1] + c0o[1];
            sg[0][r0 + 8]  = c0e[2] + c0o[2];  sg[1][r0 + 8]  = c0e[3] + c0o[3];
            sg[0][r0 + 16] = c1e[0] + c1o[0];  sg[1][r0 + 16] = c1e[1] + c1o[1];
            sg[0][r0 + 24] = c1e[2] + c1o[2];  sg[1][r0 + 24] = c1e[3] + c1o[3];
        }
        __syncthreads();

        if (tid < 256) {
            const uint2 xv = xq[s & 1];
            // prefetch step s+2 into the slot just consumed
            if (s + 2 < T_) xq[s & 1] = xqp[(long)(t + 2 * dt) * 128];
            float2 xif = __half22float2(*(const __half2*)&xv.x);  // (i, f)
            float2 xgo = __half22float2(*(const __half2*)&xv.y);  // (g, o)
            float gi = sg[cn][ci]       + xif.x;
            float gf = sg[cn][128 + ci] + xif.y;
            float gg = sg[cn][256 + ci] + xgo.x;
            float go = sg[cn][384 + ci] + xgo.y;
            gi = fast_sigmoid(gi);
            gf = fast_sigmoid(gf);
            gg = fast_tanh(gg);
            go = fast_sigmoid(go);
            float ccs = fmaf(gf, cst, gi * gg);
            cst = ccs;
            float hv = go * fast_tanh(ccs);
            hout[(long)t * (2 * H_)] = hv;
            sh16[cn][ci] = __float2half(hv);
        }
        __syncthreads();
    }
}

// ==========================================================================
// Kernel 3: logits + CRF emission precompute (unchanged).
// ==========================================================================
__global__ void __launch_bounds__(256) k_logits(
    const float* __restrict__ fcW, const float* __restrict__ fcb,
    float* __restrict__ logits)
{
    __shared__ float sW[20 * 257];
    __shared__ float shh[16 * 257];
    __shared__ float sl[16 * 20];
    const int tid = threadIdx.x;
    const long bt0 = (long)blockIdx.x * 16;

    for (int i = tid; i < 20 * 256; i += 256) {
        int cc = i >> 8, k = i & 255;
        sW[cc * 257 + k] = fcW[i];
    }
    for (int i = tid; i < 16 * 256; i += 256) {
        int tk = i >> 8, k = i & 255;
        shh[tk * 257 + k] = g_h[(bt0 + tk) * 256 + k];
    }
    __syncthreads();
    for (int o = tid; o < 16 * 20; o += 256) {
        int tk = o / 20, cc = o % 20;
        const float* hr = shh + tk * 257;
        const float* wr = sW  + cc * 257;
        float a0 = 0.f, a1 = 0.f, a2 = 0.f, a3 = 0.f;
#pragma unroll 16
        for (int k = 0; k < 256; k += 4) {
            a0 = fmaf(hr[k + 0], wr[k + 0], a0);
            a1 = fmaf(hr[k + 1], wr[k + 1], a1);
            a2 = fmaf(hr[k + 2], wr[k + 2], a2);
            a3 = fmaf(hr[k + 3], wr[k + 3], a3);
        }
        float lv = fcb[cc] + ((a0 + a1) + (a2 + a3));
        sl[o] = lv;
        logits[(bt0 + tk) * C_ + cc] = lv;
    }
    __syncthreads();
    for (int o = tid; o < 16 * 20; o += 256) {
        int tk = o / 20, cc = o % 20;
        g_eexp[(bt0 + tk) * C_ + cc] = __expf(sl[o] - sl[tk * 20]);
        if (cc == 0) g_em0[bt0 + tk] = sl[tk * 20];
    }
}

// ==========================================================================
// Kernel 4: CRF — exp-space scan from SMEM-resident tables (unchanged).
// ==========================================================================
__global__ void __launch_bounds__(128) k_crf(
    const float* __restrict__ logits,
    const int*   __restrict__ tags,
    const void*  __restrict__ maskp,
    const float* __restrict__ trans)
{
    __shared__ __align__(16) float sEE[T_ * C_];
    __shared__ __align__(16) float sEM0[T_];
    __shared__ float sT[400];
    __shared__ float sPart[8];
    const int tid  = threadIdx.x;
    const int lane = tid & 31;
    const int wid  = tid >> 5;
    const int b    = blockIdx.x;
    const int isbyte = (((const int*)maskp)[0] == 0x01010101);
    const long mbase = (long)b * T_;

    {
        const float4* src = (const float4*)(g_eexp + mbase * C_);
        float4* dst = (float4*)sEE;
        for (int i = tid; i < (T_ * C_) / 4; i += 128) dst[i] = src[i];
        const float4* s2 = (const float4*)(g_em0 + mbase);
        float4* d2 = (float4*)sEM0;
        for (int i = tid; i < T_ / 4; i += 128) d2[i] = s2[i];
    }
    for (int i = tid; i < 400; i += 128) sT[i] = trans[i];

    int lcnt = 0;
    for (int t = tid; t < T_; t += 128)
        lcnt += (load_mask(maskp, mbase + t, isbyte) != 0);
    for (int o = 16; o; o >>= 1) lcnt += __shfl_xor_sync(0xffffffffu, lcnt, o);
    if (lane == 0) sPart[4 + wid] = (float)lcnt;
    __syncthreads();
    const int len = (int)(sPart[4] + sPart[5] + sPart[6] + sPart[7]);

    const float* lg = logits + mbase * C_;

    if (wid == 0) {
        float Ecol[20];
#pragma unroll
        for (int i = 0; i < 20; i++)
            Ecol[i] = (lane < 20) ? __expf(sT[i * 20 + lane]) : 0.0f;

        float u = (lane < 20) ? sEE[lane] : 0.0f;
        float L = sEM0[0];

        for (int t = 1; t < len; t++) {
            float eeC  = (lane < 20) ? sEE[t * C_ + lane] : 0.0f;
            float em0C = sEM0[t];
            float s0 = 0.f, s1 = 0.f, s2 = 0.f, s3 = 0.f;
#pragma unroll
            for (int i = 0; i < 20; i += 4) {
                s0 = fmaf(__shfl_sync(0xffffffffu, u, i + 0), Ecol[i + 0], s0);
                s1 = fmaf(__shfl_sync(0xffffffffu, u, i + 1), Ecol[i + 1], s1);
                s2 = fmaf(__shfl_sync(0xffffffffu, u, i + 2), Ecol[i + 2], s2);
                s3 = fmaf(__shfl_sync(0xffffffffu, u, i + 3), Ecol[i + 3], s3);
            }
            u = eeC * ((s0 + s1) + (s2 + s3));
            L += em0C;
            if ((t & 3) == 0) {
                float k = __shfl_sync(0xffffffffu, u, 0);
                u *= __fdividef(1.0f, k);
                L += __logf(k);
            }
        }
        float e = u;
        for (int o = 16; o; o >>= 1) e += __shfl_xor_sync(0xffffffffu, e, o);
        if (lane == 0) sPart[0] = L + __logf(e);
    } else {
        const int id = tid - 32;
        float sn = 0.0f;
        for (int t = id; t < len; t += 96)
            sn += lg[t * C_ + tags[mbase + t]];
        for (int t = id; t < len - 1; t += 96)
            sn += sT[tags[mbase + t] * 20 + tags[mbase + t + 1]];
        for (int o = 16; o; o >>= 1) sn += __shfl_xor_sync(0xffffffffu, sn, o);
        if (lane == 0) sPart[wid] = sn;
    }
    __syncthreads();
    if (tid == 0)
        g_res[b] = sPart[0] - (sPart[1] + sPart[2] + sPart[3]);
}

// Kernel 5: deterministic mean over batches -> loss
__global__ void k_final(float* __restrict__ out)
{
    const int lane = threadIdx.x;
    float v = g_res[lane] + g_res[lane + 32];
    for (int o = 16; o; o >>= 1) v += __shfl_xor_sync(0xffffffffu, v, o);
    if (lane == 0) out[0] = v * (1.0f / 64.0f);
}

// ==========================================================================
extern "C" void kernel_launch(void* const* d_in, const int* in_sizes, int n_in,
                              void* d_out, int out_size)
{
    const int*   x      = (const int*)  d_in[0];
    const void*  mask   =               d_in[1];
    const int*   tags   = (const int*)  d_in[2];
    const float* emb    = (const float*)d_in[3];
    const float* W_ih_f = (const float*)d_in[4];
    const float* W_hh_f = (const float*)d_in[5];
    const float* b_ih_f = (const float*)d_in[6];
    const float* b_hh_f = (const float*)d_in[7];
    const float* W_ih_b = (const float*)d_in[8];
    const float* W_hh_b = (const float*)d_in[9];
    const float* b_ih_b = (const float*)d_in[10];
    const float* b_hh_b = (const float*)d_in[11];
    const float* fc_W   = (const float*)d_in[12];
    const float* fc_b   = (const float*)d_in[13];
    const float* trans  = (const float*)d_in[14];

    float* out        = (float*)d_out;
    float* loss_ptr   = out;
    float* logits_ptr = out + 1;
    if (out_size == BT_ * C_) {
        logits_ptr = out;
        loss_ptr   = nullptr;
    }

    const int gemm_smem = 2 * 3 * 5120 * 2;             // 61440 B
    cudaFuncSetAttribute(k_input_gemm,
                         cudaFuncAttributeMaxDynamicSharedMemorySize, gemm_smem);

    {
        long ntot = (long)BT_ * (KP_ / 2) + (long)2 * G4_ * (KP_ / 2);
        int nblk = (int)((ntot + 255) / 256);
        k_cvt<<<nblk, 256>>>(x, emb, W_ih_f, W_ih_b);
        k_bias<<<(2 * G4_ + 255) / 256, 256>>>(b_ih_f, b_hh_f, b_ih_b, b_hh_b);
    }
    k_input_gemm<<<dim3(8, 256), 256, gemm_smem>>>();
    k_lstm<<<64, 512>>>(W_hh_f, W_hh_b);
    k_logits<<<BT_ / 16, 256>>>(fc_W, fc_b, logits_ptr);
    k_crf<<<B_, 128>>>(logits_ptr, tags, mask, trans);
    if (loss_ptr) k_final<<<1, 32>>>(loss_ptr);
}

// round 15
// speedup vs baseline: 1.3182x; 1.3182x over previous
#include <cuda_runtime.h>
#include <cuda_fp16.h>
#include <cstdint>

#define B_   64
#define T_   512
#define H_   128
#define E_   300
#define C_   20
#define G4_  512
#define BT_  (B_ * T_)          // 32768
#define KP_  320                // K padded for fp16 tables
#define GP_  40                 // GEMM smem pitch in halves

// -------- scratch (static device globals; no runtime allocation) -----------
__device__ __align__(16) __half g_xembh[(unsigned)BT_ * KP_];  // 21 MB
__device__ __align__(16) __half g_Wh[2u * G4_ * KP_];          // 0.66 MB
__device__ __align__(16) __half g_xwh[2u * BT_ * G4_];         // 64 MB
__device__ __align__(16) float g_h [(unsigned)BT_ * 2 * H_];   // 32 MB
__device__ __align__(16) float g_eexp[(unsigned)BT_ * C_];
__device__ float g_em0[BT_];
__device__ float g_res[B_];
__device__ float g_bias[2 * G4_];

// ----------------------------- math helpers --------------------------------
__device__ __forceinline__ float fast_sigmoid(float x) {
    return __fdividef(1.0f, 1.0f + __expf(-x));
}
__device__ __forceinline__ float fast_tanh(float x) {
    float ax = fabsf(x);
    float e  = __expf(-2.0f * ax);
    float t  = __fdividef(1.0f - e, 1.0f + e);
    return copysignf(t, x);
}
__device__ __forceinline__ int load_mask(const void* m, long idx, int isbyte) {
    return isbyte ? (int)((const unsigned char*)m)[idx] : ((const int*)m)[idx];
}
__device__ __forceinline__ void ldsm4(unsigned& r0, unsigned& r1,
                                      unsigned& r2, unsigned& r3,
                                      unsigned addr) {
    asm volatile("ldmatrix.sync.aligned.m8n8.x4.shared.b16 {%0,%1,%2,%3}, [%4];"
                 : "=r"(r0), "=r"(r1), "=r"(r2), "=r"(r3) : "r"(addr));
}
__device__ __forceinline__ void mma16816(float* c,
                                         unsigned a0, unsigned a1,
                                         unsigned a2, unsigned a3,
                                         unsigned b0, unsigned b1) {
    asm volatile("mma.sync.aligned.m16n8k16.row.col.f32.f16.f16.f32 "
                 "{%0,%1,%2,%3}, {%4,%5,%6,%7}, {%8,%9}, {%0,%1,%2,%3};"
                 : "+f"(c[0]), "+f"(c[1]), "+f"(c[2]), "+f"(c[3])
                 : "r"(a0), "r"(a1), "r"(a2), "r"(a3), "r"(b0), "r"(b1));
}
__device__ __forceinline__ void cp16(unsigned dst, const void* src) {
    asm volatile("cp.async.cg.shared.global [%0], [%1], 16;"
                 :: "r"(dst), "l"(src));
}
__device__ __forceinline__ void cp_commit() {
    asm volatile("cp.async.commit_group;");
}
template <int N>
__device__ __forceinline__ void cp_wait() {
    asm volatile("cp.async.wait_group %0;" :: "n"(N));
}

// ==========================================================================
// Kernel 0: per-token fp16 embedding gather-convert + W_ih convert.
// ==========================================================================
__global__ void __launch_bounds__(256) k_cvt(
    const int*   __restrict__ x,
    const float* __restrict__ emb,
    const float* __restrict__ Wf, const float* __restrict__ Wb)
{
    const long NE = (long)BT_ * (KP_ / 2);
    const long NW = (long)2 * G4_ * (KP_ / 2);
    long i = (long)blockIdx.x * 256 + threadIdx.x;
    if (i < NE) {
        long bt  = i / (KP_ / 2);
        int  col = 2 * (int)(i % (KP_ / 2));
        __half2 v;
        if (col < 300) {
            const float* s = emb + (long)x[bt] * 300 + col;
            v = __floats2half2_rn(s[0], s[1]);
        } else v = __floats2half2_rn(0.f, 0.f);
        ((__half2*)g_xembh)[i] = v;
    } else if (i < NE + NW) {
        long j   = i - NE;
        long row = j / (KP_ / 2);
        int  col = 2 * (int)(j % (KP_ / 2));
        const float* W = (row < G4_) ? Wf : Wb;
        long r = (row < G4_) ? row : row - G4_;
        __half2 v;
        if (col < 300) {
            const float* s = W + r * 300 + col;
            v = __floats2half2_rn(s[0], s[1]);
        } else v = __floats2half2_rn(0.f, 0.f);
        ((__half2*)g_Wh)[j] = v;
    }
}

__global__ void k_bias(const float* __restrict__ bif, const float* __restrict__ bhf,
                       const float* __restrict__ bib, const float* __restrict__ bhb)
{
    int i = blockIdx.x * 256 + threadIdx.x;
    if (i < G4_)          g_bias[i] = bif[i] + bhf[i];
    else if (i < 2 * G4_) g_bias[i] = bib[i - G4_] + bhb[i - G4_];
}

// ==========================================================================
// Kernel 1: input GEMM — HMMA + cp.async 3-stage; sequential A (R13 exact).
// ==========================================================================
__global__ void __launch_bounds__(256, 2) k_input_gemm()
{
    extern __shared__ __align__(16) char gsm[];
    __half* sA = (__half*)gsm;
    __half* sB = (__half*)(gsm + 3 * 5120 * 2);

    const int tid   = threadIdx.x;
    const int lane  = tid & 31;
    const int wid   = tid >> 5;
    const int wm    = wid >> 1;
    const int wn    = wid & 1;
    const int m0    = blockIdx.y * 128;
    const int n0g   = blockIdx.x * 128;
    const int dir   = n0g >> 9;
    const int gbase = n0g & 511;

    const int  lrow = tid >> 1;
    const int  hoff = (tid & 1) * 16;
    const __half* srcA = g_xembh + (long)(m0 + lrow) * KP_ + hoff;
    const __half* srcB = g_Wh + ((long)dir * G4_ + gbase + lrow) * KP_ + hoff;
    const unsigned sAb = (unsigned)__cvta_generic_to_shared(sA);
    const unsigned sBb = (unsigned)__cvta_generic_to_shared(sB);
    const unsigned dA0 = sAb + (unsigned)((lrow * GP_ + hoff) * 2);
    const unsigned dB0 = sBb + (unsigned)((lrow * GP_ + hoff) * 2);

    float cacc[2][8][4];
#pragma unroll
    for (int mt = 0; mt < 2; mt++)
#pragma unroll
        for (int nt = 0; nt < 8; nt++)
#pragma unroll
            for (int r = 0; r < 4; r++) cacc[mt][nt][r] = 0.0f;

    auto ISSUE = [&](int s) {
        const unsigned bo = (unsigned)((s % 3) * 5120 * 2);
        const __half* a = srcA + s * 32;
        const __half* b = srcB + s * 32;
        cp16(dA0 + bo,      a);
        cp16(dA0 + bo + 16, a + 8);
        cp16(dB0 + bo,      b);
        cp16(dB0 + bo + 16, b + 8);
        cp_commit();
    };

    ISSUE(0); ISSUE(1);

    for (int ks = 0; ks < 10; ks++) {
        cp_wait<1>();
        __syncthreads();
        if (ks < 8) ISSUE(ks + 2);

        const unsigned bo = (unsigned)((ks % 3) * 5120 * 2);
        const unsigned bA = sAb + bo;
        const unsigned bB = sBb + bo;
#pragma unroll
        for (int ks2 = 0; ks2 < 2; ks2++) {
            const int k0 = ks2 * 16;
            unsigned a[2][4];
#pragma unroll
            for (int mt = 0; mt < 2; mt++) {
                int row = wm * 32 + mt * 16 + (lane & 15);
                unsigned ad = bA + (unsigned)((row * GP_ + k0 + (lane >> 4) * 8) * 2);
                ldsm4(a[mt][0], a[mt][1], a[mt][2], a[mt][3], ad);
            }
            unsigned b[8][2];
#pragma unroll
            for (int ntp = 0; ntp < 4; ntp++) {
                int nr = wn * 64 + ntp * 16 + (lane & 7) + (lane >> 4) * 8;
                unsigned ad = bB + (unsigned)((nr * GP_ + k0 + ((lane >> 3) & 1) * 8) * 2);
                unsigned r0, r1, r2, r3;
                ldsm4(r0, r1, r2, r3, ad);
                b[2*ntp][0] = r0;  b[2*ntp][1] = r1;
                b[2*ntp+1][0] = r2; b[2*ntp+1][1] = r3;
            }
#pragma unroll
            for (int mt = 0; mt < 2; mt++)
#pragma unroll
                for (int nt = 0; nt < 8; nt++)
                    mma16816(cacc[mt][nt], a[mt][0], a[mt][1], a[mt][2], a[mt][3],
                             b[nt][0], b[nt][1]);
        }
    }

    const int qr = lane >> 2;
    const int qc = (lane & 3) * 2;
    __half* outbase = g_xwh + (long)dir * BT_ * G4_;
    const float* bsum = g_bias + dir * G4_;
#pragma unroll
    for (int nt = 0; nt < 8; nt++) {
        int gc = gbase + wn * 64 + nt * 8 + qc;
        float bx = bsum[gc];
        float by = bsum[gc + 1];
#pragma unroll
        for (int mt = 0; mt < 2; mt++) {
            long gm = m0 + wm * 32 + mt * 16 + qr;
            __half* o = outbase + gm * G4_ + gc;
            *(__half2*)o             = __floats2half2_rn(cacc[mt][nt][0] + bx,
                                                         cacc[mt][nt][1] + by);
            *(__half2*)(o + 8 * G4_) = __floats2half2_rn(cacc[mt][nt][2] + bx,
                                                         cacc[mt][nt][3] + by);
        }
    }
}

// ==========================================================================
// Kernel 2: LSTM v4r3 — R13 structure; time loop unrolled by 2 with two
//   NAMED register sets for a depth-2 xw prefetch (no dynamic indexing,
//   no spill). Original g_xwh layout.
// ==========================================================================
__global__ void __launch_bounds__(512) k_lstm(
    const float* __restrict__ Whf, const float* __restrict__ Whb)
{
    __shared__ __half sh16[2][128];     // h per batch (fp16, k-contiguous)
    __shared__ float  sg[2][512];       // gates per batch

    const int tid  = threadIdx.x;
    const int lane = tid & 31;
    const int wid  = tid >> 5;          // 0..15
    const int dir  = blockIdx.x >> 5;
    const int bg   = blockIdx.x & 31;   // batches 2bg, 2bg+1
    const float* Wh = dir ? Whb : Whf;

    // A-fragment preload (rows = gates, cols = k), once.
    unsigned afr[2][8][4];
    {
        const int g = lane >> 2, t4 = lane & 3;
#pragma unroll
        for (int mt = 0; mt < 2; mt++) {
            int r0 = wid * 32 + mt * 16 + g;
#pragma unroll
            for (int ks = 0; ks < 8; ks++) {
                int k0 = ks * 16 + 2 * t4;
                float2 w00 = *(const float2*)(Wh + (long)r0 * 128 + k0);
                float2 w10 = *(const float2*)(Wh + (long)(r0 + 8) * 128 + k0);
                float2 w01 = *(const float2*)(Wh + (long)r0 * 128 + k0 + 8);
                float2 w11 = *(const float2*)(Wh + (long)(r0 + 8) * 128 + k0 + 8);
                __half2 h00 = __floats2half2_rn(w00.x, w00.y);
                __half2 h10 = __floats2half2_rn(w10.x, w10.y);
                __half2 h01 = __floats2half2_rn(w01.x, w01.y);
                __half2 h11 = __floats2half2_rn(w11.x, w11.y);
                afr[mt][ks][0] = *(unsigned*)&h00;
                afr[mt][ks][1] = *(unsigned*)&h10;
                afr[mt][ks][2] = *(unsigned*)&h01;
                afr[mt][ks][3] = *(unsigned*)&h11;
            }
        }
    }

    if (tid < 256) {
        int n = tid >> 7, i = tid & 127;
        sh16[n][i] = __float2half(0.0f);
    }
    float cst = 0.0f;
    __syncthreads();

    const int cn = tid >> 7;            // cell-update batch (tid<256)
    const int ci = tid & 127;           // cell-update h index
    const long xwrow0 = ((long)dir * BT_ + (long)(2 * bg + cn) * T_) * G4_;
    const __half* xwb = g_xwh + xwrow0 + ci;
    float* hout = g_h + ((long)(2 * bg + cn) * T_) * (2 * H_) + dir * H_ + ci;

    int t  = dir ? (T_ - 1) : 0;
    const int dt = dir ? -1 : 1;

    // depth-2 prefetch: named register sets A (even s) and B (odd s)
    __half xa0, xa1, xa2, xa3, xb0, xb1, xb2, xb3;
    if (tid < 256) {
        const __half* p = xwb + (long)t * G4_;
        xa0 = p[0]; xa1 = p[128]; xa2 = p[256]; xa3 = p[384];
        const __half* q = xwb + (long)(t + dt) * G4_;
        xb0 = q[0]; xb1 = q[128]; xb2 = q[256]; xb3 = q[384];
    }

    const int bn = lane >> 2;           // B-frag column (batch if < 2)
    const int bk = (lane & 3) * 2;      // B-frag k base

    // one LSTM step; xw passed in named regs, refill for t+2dt
    auto STEP = [&](int tcur, __half& x0, __half& x1, __half& x2, __half& x3) {
        float c0e[4] = {0,0,0,0}, c0o[4] = {0,0,0,0};
        float c1e[4] = {0,0,0,0}, c1o[4] = {0,0,0,0};
#pragma unroll
        for (int ks = 0; ks < 8; ks += 2) {
            unsigned b0 = 0, b1 = 0, b2 = 0, b3 = 0;
            if (bn < 2) {
                b0 = *(const unsigned*)&sh16[bn][ks * 16 + bk];
                b1 = *(const unsigned*)&sh16[bn][ks * 16 + bk + 8];
                b2 = *(const unsigned*)&sh16[bn][ks * 16 + 16 + bk];
                b3 = *(const unsigned*)&sh16[bn][ks * 16 + 16 + bk + 8];
            }
            mma16816(c0e, afr[0][ks][0], afr[0][ks][1], afr[0][ks][2],
                     afr[0][ks][3], b0, b1);
            mma16816(c1e, afr[1][ks][0], afr[1][ks][1], afr[1][ks][2],
                     afr[1][ks][3], b0, b1);
            mma16816(c0o, afr[0][ks+1][0], afr[0][ks+1][1], afr[0][ks+1][2],
                     afr[0][ks+1][3], b2, b3);
            mma16816(c1o, afr[1][ks+1][0], afr[1][ks+1][1], afr[1][ks+1][2],
                     afr[1][ks+1][3], b2, b3);
        }
        if ((lane & 3) == 0) {
            int r0 = wid * 32 + (lane >> 2);
            sg[0][r0]      = c0e[0] + c0o[0];  sg[1][r0]      = c0e[1] + c0o[1];
            sg[0][r0 + 8]  = c0e[2] + c0o[2];  sg[1][r0 + 8]  = c0e[3] + c0o[3];
            sg[0][r0 + 16] = c1e[0] + c1o[0];  sg[1][r0 + 16] = c1e[1] + c1o[1];
            sg[0][r0 + 24] = c1e[2] + c1o[2];  sg[1][r0 + 24] = c1e[3] + c1o[3];
        }
        __syncthreads();

        if (tid < 256) {
            float gi = sg[cn][ci]       + __half2float(x0);
            float gf = sg[cn][128 + ci] + __half2float(x1);
            float gg = sg[cn][256 + ci] + __half2float(x2);
            float go = sg[cn][384 + ci] + __half2float(x3);
            // refill this parity's regs from t+2dt (2-step lead)
            int tn = tcur + 2 * dt;
            if (tn >= 0 && tn < T_) {
                const __half* p = xwb + (long)tn * G4_;
                x0 = p[0]; x1 = p[128]; x2 = p[256]; x3 = p[384];
            }
            gi = fast_sigmoid(gi);
            gf = fast_sigmoid(gf);
            gg = fast_tanh(gg);
            go = fast_sigmoid(go);
            float ccs = fmaf(gf, cst, gi * gg);
            cst = ccs;
            float hv = go * fast_tanh(ccs);
            hout[(long)tcur * (2 * H_)] = hv;
            sh16[cn][ci] = __float2half(hv);
        }
        __syncthreads();
    };

    for (int s = 0; s < T_; s += 2, t += 2 * dt) {
        STEP(t,      xa0, xa1, xa2, xa3);
        STEP(t + dt, xb0, xb1, xb2, xb3);
    }
}

// ==========================================================================
// Kernel 3: logits + CRF emission precompute (unchanged).
// ==========================================================================
__global__ void __launch_bounds__(256) k_logits(
    const float* __restrict__ fcW, const float* __restrict__ fcb,
    float* __restrict__ logits)
{
    __shared__ float sW[20 * 257];
    __shared__ float shh[16 * 257];
    __shared__ float sl[16 * 20];
    const int tid = threadIdx.x;
    const long bt0 = (long)blockIdx.x * 16;

    for (int i = tid; i < 20 * 256; i += 256) {
        int cc = i >> 8, k = i & 255;
        sW[cc * 257 + k] = fcW[i];
    }
    for (int i = tid; i < 16 * 256; i += 256) {
        int tk = i >> 8, k = i & 255;
        shh[tk * 257 + k] = g_h[(bt0 + tk) * 256 + k];
    }
    __syncthreads();
    for (int o = tid; o < 16 * 20; o += 256) {
        int tk = o / 20, cc = o % 20;
        const float* hr = shh + tk * 257;
        const float* wr = sW  + cc * 257;
        float a0 = 0.f, a1 = 0.f, a2 = 0.f, a3 = 0.f;
#pragma unroll 16
        for (int k = 0; k < 256; k += 4) {
            a0 = fmaf(hr[k + 0], wr[k + 0], a0);
            a1 = fmaf(hr[k + 1], wr[k + 1], a1);
            a2 = fmaf(hr[k + 2], wr[k + 2], a2);
            a3 = fmaf(hr[k + 3], wr[k + 3], a3);
        }
        float lv = fcb[cc] + ((a0 + a1) + (a2 + a3));
        sl[o] = lv;
        logits[(bt0 + tk) * C_ + cc] = lv;
    }
    __syncthreads();
    for (int o = tid; o < 16 * 20; o += 256) {
        int tk = o / 20, cc = o % 20;
        g_eexp[(bt0 + tk) * C_ + cc] = __expf(sl[o] - sl[tk * 20]);
        if (cc == 0) g_em0[bt0 + tk] = sl[tk * 20];
    }
}

// ==========================================================================
// Kernel 4: CRF — exp-space scan from SMEM-resident tables (unchanged).
// ==========================================================================
__global__ void __launch_bounds__(128) k_crf(
    const float* __restrict__ logits,
    const int*   __restrict__ tags,
    const void*  __restrict__ maskp,
    const float* __restrict__ trans)
{
    __shared__ __align__(16) float sEE[T_ * C_];
    __shared__ __align__(16) float sEM0[T_];
    __shared__ float sT[400];
    __shared__ float sPart[8];
    const int tid  = threadIdx.x;
    const int lane = tid & 31;
    const int wid  = tid >> 5;
    const int b    = blockIdx.x;
    const int isbyte = (((const int*)maskp)[0] == 0x01010101);
    const long mbase = (long)b * T_;

    {
        const float4* src = (const float4*)(g_eexp + mbase * C_);
        float4* dst = (float4*)sEE;
        for (int i = tid; i < (T_ * C_) / 4; i += 128) dst[i] = src[i];
        const float4* s2 = (const float4*)(g_em0 + mbase);
        float4* d2 = (float4*)sEM0;
        for (int i = tid; i < T_ / 4; i += 128) d2[i] = s2[i];
    }
    for (int i = tid; i < 400; i += 128) sT[i] = trans[i];

    int lcnt = 0;
    for (int t = tid; t < T_; t += 128)
        lcnt += (load_mask(maskp, mbase + t, isbyte) != 0);
    for (int o = 16; o; o >>= 1) lcnt += __shfl_xor_sync(0xffffffffu, lcnt, o);
    if (lane == 0) sPart[4 + wid] = (float)lcnt;
    __syncthreads();
    const int len = (int)(sPart[4] + sPart[5] + sPart[6] + sPart[7]);

    const float* lg = logits + mbase * C_;

    if (wid == 0) {
        float Ecol[20];
#pragma unroll
        for (int i = 0; i < 20; i++)
            Ecol[i] = (lane < 20) ? __expf(sT[i * 20 + lane]) : 0.0f;

        float u = (lane < 20) ? sEE[lane] : 0.0f;
        float L = sEM0[0];

        for (int t = 1; t < len; t++) {
            float eeC  = (lane < 20) ? sEE[t * C_ + lane] : 0.0f;
            float em0C = sEM0[t];
            float s0 = 0.f, s1 = 0.f, s2 = 0.f, s3 = 0.f;
#pragma unroll
            for (int i = 0; i < 20; i += 4) {
                s0 = fmaf(__shfl_sync(0xffffffffu, u, i + 0), Ecol[i + 0], s0);
                s1 = fmaf(__shfl_sync(0xffffffffu, u, i + 1), Ecol[i + 1], s1);
                s2 = fmaf(__shfl_sync(0xffffffffu, u, i + 2), Ecol[i + 2], s2);
                s3 = fmaf(__shfl_sync(0xffffffffu, u, i + 3), Ecol[i + 3], s3);
            }
            u = eeC * ((s0 + s1) + (s2 + s3));
            L += em0C;
            if ((t & 3) == 0) {
                float k = __shfl_sync(0xffffffffu, u, 0);
                u *= __fdividef(1.0f, k);
                L += __logf(k);
            }
        }
        float e = u;
        for (int o = 16; o; o >>= 1) e += __shfl_xor_sync(0xffffffffu, e, o);
        if (lane == 0) sPart[0] = L + __logf(e);
    } else {
        const int id = tid - 32;
        float sn = 0.0f;
        for (int t = id; t < len; t += 96)
            sn += lg[t * C_ + tags[mbase + t]];
        for (int t = id; t < len - 1; t += 96)
            sn += sT[tags[mbase + t] * 20 + tags[mbase + t + 1]];
        for (int o = 16; o; o >>= 1) sn += __shfl_xor_sync(0xffffffffu, sn, o);
        if (lane == 0) sPart[wid] = sn;
    }
    __syncthreads();
    if (tid == 0)
        g_res[b] = sPart[0] - (sPart[1] + sPart[2] + sPart[3]);
}

// Kernel 5: deterministic mean over batches -> loss
__global__ void k_final(float* __restrict__ out)
{
    const int lane = threadIdx.x;
    float v = g_res[lane] + g_res[lane + 32];
    for (int o = 16; o; o >>= 1) v += __shfl_xor_sync(0xffffffffu, v, o);
    if (lane == 0) out[0] = v * (1.0f / 64.0f);
}

// ==========================================================================
extern "C" void kernel_launch(void* const* d_in, const int* in_sizes, int n_in,
                              void* d_out, int out_size)
{
    const int*   x      = (const int*)  d_in[0];
    const void*  mask   =               d_in[1];
    const int*   tags   = (const int*)  d_in[2];
    const float* emb    = (const float*)d_in[3];
    const float* W_ih_f = (const float*)d_in[4];
    const float* W_hh_f = (const float*)d_in[5];
    const float* b_ih_f = (const float*)d_in[6];
    const float* b_hh_f = (const float*)d_in[7];
    const float* W_ih_b = (const float*)d_in[8];
    const float* W_hh_b = (const float*)d_in[9];
    const float* b_ih_b = (const float*)d_in[10];
    const float* b_hh_b = (const float*)d_in[11];
    const float* fc_W   = (const float*)d_in[12];
    const float* fc_b   = (const float*)d_in[13];
    const float* trans  = (const float*)d_in[14];

    float* out        = (float*)d_out;
    float* loss_ptr   = out;
    float* logits_ptr = out + 1;
    if (out_size == BT_ * C_) {
        logits_ptr = out;
        loss_ptr   = nullptr;
    }

    const int gemm_smem = 2 * 3 * 5120 * 2;             // 61440 B
    cudaFuncSetAttribute(k_input_gemm,
                         cudaFuncAttributeMaxDynamicSharedMemorySize, gemm_smem);

    {
        long ntot = (long)BT_ * (KP_ / 2) + (long)2 * G4_ * (KP_ / 2);
        int nblk = (int)((ntot + 255) / 256);
        k_cvt<<<nblk, 256>>>(x, emb, W_ih_f, W_ih_b);
        k_bias<<<(2 * G4_ + 255) / 256, 256>>>(b_ih_f, b_hh_f, b_ih_b, b_hh_b);
    }
    k_input_gemm<<<dim3(8, 256), 256, gemm_smem>>>();
    k_lstm<<<64, 512>>>(W_hh_f, W_hh_b);
    k_logits<<<BT_ / 16, 256>>>(fc_W, fc_b, logits_ptr);
    k_crf<<<B_, 128>>>(logits_ptr, tags, mask, trans);
    if (loss_ptr) k_final<<<1, 32>>>(loss_ptr);
}

// round 16
// speedup vs baseline: 1.4896x; 1.1300x over previous
#include <cuda_runtime.h>
#include <cuda_fp16.h>
#include <cstdint>

#define B_   64
#define T_   512
#define H_   128
#define E_   300
#define C_   20
#define G4_  512
#define BT_  (B_ * T_)          // 32768
#define KP_  320                // K padded for fp16 tables
#define GP_  40                 // GEMM smem pitch in halves

// -------- scratch (static device globals; no runtime allocation) -----------
__device__ __align__(16) __half g_xembh[(unsigned)BT_ * KP_];  // 21 MB
__device__ __align__(16) __half g_Wh[2u * G4_ * KP_];          // 0.66 MB
__device__ __align__(16) __half g_xwh[2u * BT_ * G4_];         // 64 MB
__device__ __align__(16) float g_h [(unsigned)BT_ * 2 * H_];   // 32 MB
__device__ __align__(16) float g_eexp[(unsigned)BT_ * C_];
__device__ float g_em0[BT_];
__device__ float g_res[B_];
__device__ float g_bias[2 * G4_];

// ----------------------------- math helpers --------------------------------
__device__ __forceinline__ float fast_sigmoid(float x) {
    return __fdividef(1.0f, 1.0f + __expf(-x));
}
__device__ __forceinline__ float fast_tanh(float x) {
    float ax = fabsf(x);
    float e  = __expf(-2.0f * ax);
    float t  = __fdividef(1.0f - e, 1.0f + e);
    return copysignf(t, x);
}
// HW tanh (sm_75+): single MUFU op, err ~2^-10.6 (same scale as the fp16
// rounding already applied to h each step).
__device__ __forceinline__ float tanh_hw(float x) {
    float y;
    asm("tanh.approx.f32 %0, %1;" : "=f"(y) : "f"(x));
    return y;
}
__device__ __forceinline__ float sigmoid_hw(float x) {
    return fmaf(tanh_hw(0.5f * x), 0.5f, 0.5f);
}
__device__ __forceinline__ int load_mask(const void* m, long idx, int isbyte) {
    return isbyte ? (int)((const unsigned char*)m)[idx] : ((const int*)m)[idx];
}
__device__ __forceinline__ void ldsm4(unsigned& r0, unsigned& r1,
                                      unsigned& r2, unsigned& r3,
                                      unsigned addr) {
    asm volatile("ldmatrix.sync.aligned.m8n8.x4.shared.b16 {%0,%1,%2,%3}, [%4];"
                 : "=r"(r0), "=r"(r1), "=r"(r2), "=r"(r3) : "r"(addr));
}
__device__ __forceinline__ void mma16816(float* c,
                                         unsigned a0, unsigned a1,
                                         unsigned a2, unsigned a3,
                                         unsigned b0, unsigned b1) {
    asm volatile("mma.sync.aligned.m16n8k16.row.col.f32.f16.f16.f32 "
                 "{%0,%1,%2,%3}, {%4,%5,%6,%7}, {%8,%9}, {%0,%1,%2,%3};"
                 : "+f"(c[0]), "+f"(c[1]), "+f"(c[2]), "+f"(c[3])
                 : "r"(a0), "r"(a1), "r"(a2), "r"(a3), "r"(b0), "r"(b1));
}
__device__ __forceinline__ void cp16(unsigned dst, const void* src) {
    asm volatile("cp.async.cg.shared.global [%0], [%1], 16;"
                 :: "r"(dst), "l"(src));
}
__device__ __forceinline__ void cp_commit() {
    asm volatile("cp.async.commit_group;");
}
template <int N>
__device__ __forceinline__ void cp_wait() {
    asm volatile("cp.async.wait_group %0;" :: "n"(N));
}

// ==========================================================================
// Kernel 0: per-token fp16 embedding gather-convert + W_ih convert.
// ==========================================================================
__global__ void __launch_bounds__(256) k_cvt(
    const int*   __restrict__ x,
    const float* __restrict__ emb,
    const float* __restrict__ Wf, const float* __restrict__ Wb)
{
    const long NE = (long)BT_ * (KP_ / 2);
    const long NW = (long)2 * G4_ * (KP_ / 2);
    long i = (long)blockIdx.x * 256 + threadIdx.x;
    if (i < NE) {
        long bt  = i / (KP_ / 2);
        int  col = 2 * (int)(i % (KP_ / 2));
        __half2 v;
        if (col < 300) {
            const float* s = emb + (long)x[bt] * 300 + col;
            v = __floats2half2_rn(s[0], s[1]);
        } else v = __floats2half2_rn(0.f, 0.f);
        ((__half2*)g_xembh)[i] = v;
    } else if (i < NE + NW) {
        long j   = i - NE;
        long row = j / (KP_ / 2);
        int  col = 2 * (int)(j % (KP_ / 2));
        const float* W = (row < G4_) ? Wf : Wb;
        long r = (row < G4_) ? row : row - G4_;
        __half2 v;
        if (col < 300) {
            const float* s = W + r * 300 + col;
            v = __floats2half2_rn(s[0], s[1]);
        } else v = __floats2half2_rn(0.f, 0.f);
        ((__half2*)g_Wh)[j] = v;
    }
}

__global__ void k_bias(const float* __restrict__ bif, const float* __restrict__ bhf,
                       const float* __restrict__ bib, const float* __restrict__ bhb)
{
    int i = blockIdx.x * 256 + threadIdx.x;
    if (i < G4_)          g_bias[i] = bif[i] + bhf[i];
    else if (i < 2 * G4_) g_bias[i] = bib[i - G4_] + bhb[i - G4_];
}

// ==========================================================================
// Kernel 1: input GEMM — HMMA + cp.async 3-stage; sequential A (R13 exact).
// ==========================================================================
__global__ void __launch_bounds__(256, 2) k_input_gemm()
{
    extern __shared__ __align__(16) char gsm[];
    __half* sA = (__half*)gsm;
    __half* sB = (__half*)(gsm + 3 * 5120 * 2);

    const int tid   = threadIdx.x;
    const int lane  = tid & 31;
    const int wid   = tid >> 5;
    const int wm    = wid >> 1;
    const int wn    = wid & 1;
    const int m0    = blockIdx.y * 128;
    const int n0g   = blockIdx.x * 128;
    const int dir   = n0g >> 9;
    const int gbase = n0g & 511;

    const int  lrow = tid >> 1;
    const int  hoff = (tid & 1) * 16;
    const __half* srcA = g_xembh + (long)(m0 + lrow) * KP_ + hoff;
    const __half* srcB = g_Wh + ((long)dir * G4_ + gbase + lrow) * KP_ + hoff;
    const unsigned sAb = (unsigned)__cvta_generic_to_shared(sA);
    const unsigned sBb = (unsigned)__cvta_generic_to_shared(sB);
    const unsigned dA0 = sAb + (unsigned)((lrow * GP_ + hoff) * 2);
    const unsigned dB0 = sBb + (unsigned)((lrow * GP_ + hoff) * 2);

    float cacc[2][8][4];
#pragma unroll
    for (int mt = 0; mt < 2; mt++)
#pragma unroll
        for (int nt = 0; nt < 8; nt++)
#pragma unroll
            for (int r = 0; r < 4; r++) cacc[mt][nt][r] = 0.0f;

    auto ISSUE = [&](int s) {
        const unsigned bo = (unsigned)((s % 3) * 5120 * 2);
        const __half* a = srcA + s * 32;
        const __half* b = srcB + s * 32;
        cp16(dA0 + bo,      a);
        cp16(dA0 + bo + 16, a + 8);
        cp16(dB0 + bo,      b);
        cp16(dB0 + bo + 16, b + 8);
        cp_commit();
    };

    ISSUE(0); ISSUE(1);

    for (int ks = 0; ks < 10; ks++) {
        cp_wait<1>();
        __syncthreads();
        if (ks < 8) ISSUE(ks + 2);

        const unsigned bo = (unsigned)((ks % 3) * 5120 * 2);
        const unsigned bA = sAb + bo;
        const unsigned bB = sBb + bo;
#pragma unroll
        for (int ks2 = 0; ks2 < 2; ks2++) {
            const int k0 = ks2 * 16;
            unsigned a[2][4];
#pragma unroll
            for (int mt = 0; mt < 2; mt++) {
                int row = wm * 32 + mt * 16 + (lane & 15);
                unsigned ad = bA + (unsigned)((row * GP_ + k0 + (lane >> 4) * 8) * 2);
                ldsm4(a[mt][0], a[mt][1], a[mt][2], a[mt][3], ad);
            }
            unsigned b[8][2];
#pragma unroll
            for (int ntp = 0; ntp < 4; ntp++) {
                int nr = wn * 64 + ntp * 16 + (lane & 7) + (lane >> 4) * 8;
                unsigned ad = bB + (unsigned)((nr * GP_ + k0 + ((lane >> 3) & 1) * 8) * 2);
                unsigned r0, r1, r2, r3;
                ldsm4(r0, r1, r2, r3, ad);
                b[2*ntp][0] = r0;  b[2*ntp][1] = r1;
                b[2*ntp+1][0] = r2; b[2*ntp+1][1] = r3;
            }
#pragma unroll
            for (int mt = 0; mt < 2; mt++)
#pragma unroll
                for (int nt = 0; nt < 8; nt++)
                    mma16816(cacc[mt][nt], a[mt][0], a[mt][1], a[mt][2], a[mt][3],
                             b[nt][0], b[nt][1]);
        }
    }

    const int qr = lane >> 2;
    const int qc = (lane & 3) * 2;
    __half* outbase = g_xwh + (long)dir * BT_ * G4_;
    const float* bsum = g_bias + dir * G4_;
#pragma unroll
    for (int nt = 0; nt < 8; nt++) {
        int gc = gbase + wn * 64 + nt * 8 + qc;
        float bx = bsum[gc];
        float by = bsum[gc + 1];
#pragma unroll
        for (int mt = 0; mt < 2; mt++) {
            long gm = m0 + wm * 32 + mt * 16 + qr;
            __half* o = outbase + gm * G4_ + gc;
            *(__half2*)o             = __floats2half2_rn(cacc[mt][nt][0] + bx,
                                                         cacc[mt][nt][1] + by);
            *(__half2*)(o + 8 * G4_) = __floats2half2_rn(cacc[mt][nt][2] + bx,
                                                         cacc[mt][nt][3] + by);
        }
    }
}

// ==========================================================================
// Kernel 2: LSTM v4r (R13 structure exactly) + HW tanh activations.
// ==========================================================================
__global__ void __launch_bounds__(512) k_lstm(
    const float* __restrict__ Whf, const float* __restrict__ Whb)
{
    __shared__ __half sh16[2][128];     // h per batch (fp16, k-contiguous)
    __shared__ float  sg[2][512];       // gates per batch

    const int tid  = threadIdx.x;
    const int lane = tid & 31;
    const int wid  = tid >> 5;          // 0..15
    const int dir  = blockIdx.x >> 5;
    const int bg   = blockIdx.x & 31;   // batches 2bg, 2bg+1
    const float* Wh = dir ? Whb : Whf;

    // A-fragment preload (rows = gates, cols = k), once.
    unsigned afr[2][8][4];
    {
        const int g = lane >> 2, t4 = lane & 3;
#pragma unroll
        for (int mt = 0; mt < 2; mt++) {
            int r0 = wid * 32 + mt * 16 + g;
#pragma unroll
            for (int ks = 0; ks < 8; ks++) {
                int k0 = ks * 16 + 2 * t4;
                float2 w00 = *(const float2*)(Wh + (long)r0 * 128 + k0);
                float2 w10 = *(const float2*)(Wh + (long)(r0 + 8) * 128 + k0);
                float2 w01 = *(const float2*)(Wh + (long)r0 * 128 + k0 + 8);
                float2 w11 = *(const float2*)(Wh + (long)(r0 + 8) * 128 + k0 + 8);
                __half2 h00 = __floats2half2_rn(w00.x, w00.y);
                __half2 h10 = __floats2half2_rn(w10.x, w10.y);
                __half2 h01 = __floats2half2_rn(w01.x, w01.y);
                __half2 h11 = __floats2half2_rn(w11.x, w11.y);
                afr[mt][ks][0] = *(unsigned*)&h00;
                afr[mt][ks][1] = *(unsigned*)&h10;
                afr[mt][ks][2] = *(unsigned*)&h01;
                afr[mt][ks][3] = *(unsigned*)&h11;
            }
        }
    }

    if (tid < 256) {
        int n = tid >> 7, i = tid & 127;
        sh16[n][i] = __float2half(0.0f);
    }
    float cst = 0.0f;
    __syncthreads();

    const int cn = tid >> 7;            // cell-update batch (tid<256)
    const int ci = tid & 127;           // cell-update h index
    const long xwrow0 = ((long)dir * BT_ + (long)(2 * bg + cn) * T_) * G4_;
    float* hout = g_h + ((long)(2 * bg + cn) * T_) * (2 * H_) + dir * H_ + ci;

    int t  = dir ? (T_ - 1) : 0;
    const int dt = dir ? -1 : 1;

    __half xn0, xn1, xn2, xn3;
    if (tid < 256) {
        const __half* p = g_xwh + xwrow0 + (long)t * G4_;
        xn0 = p[ci]; xn1 = p[128 + ci]; xn2 = p[256 + ci]; xn3 = p[384 + ci];
    }

    const int bn = lane >> 2;           // B-frag column (batch if < 2)
    const int bk = (lane & 3) * 2;      // B-frag k base

    for (int s = 0; s < T_; s++, t += dt) {
        // matvec, split even/odd-ks chains (HMMA dependency depth 4)
        float c0e[4] = {0,0,0,0}, c0o[4] = {0,0,0,0};
        float c1e[4] = {0,0,0,0}, c1o[4] = {0,0,0,0};
#pragma unroll
        for (int ks = 0; ks < 8; ks += 2) {
            unsigned b0 = 0, b1 = 0, b2 = 0, b3 = 0;
            if (bn < 2) {
                b0 = *(const unsigned*)&sh16[bn][ks * 16 + bk];
                b1 = *(const unsigned*)&sh16[bn][ks * 16 + bk + 8];
                b2 = *(const unsigned*)&sh16[bn][ks * 16 + 16 + bk];
                b3 = *(const unsigned*)&sh16[bn][ks * 16 + 16 + bk + 8];
            }
            mma16816(c0e, afr[0][ks][0], afr[0][ks][1], afr[0][ks][2],
                     afr[0][ks][3], b0, b1);
            mma16816(c1e, afr[1][ks][0], afr[1][ks][1], afr[1][ks][2],
                     afr[1][ks][3], b0, b1);
            mma16816(c0o, afr[0][ks+1][0], afr[0][ks+1][1], afr[0][ks+1][2],
                     afr[0][ks+1][3], b2, b3);
            mma16816(c1o, afr[1][ks+1][0], afr[1][ks+1][1], afr[1][ks+1][2],
                     afr[1][ks+1][3], b2, b3);
        }
        if ((lane & 3) == 0) {
            int r0 = wid * 32 + (lane >> 2);
            sg[0][r0]      = c0e[0] + c0o[0];  sg[1][r0]      = c0e[1] + c0o[1];
            sg[0][r0 + 8]  = c0e[2] + c0o[2];  sg[1][r0 + 8]  = c0e[3] + c0o[3];
            sg[0][r0 + 16] = c1e[0] + c1o[0];  sg[1][r0 + 16] = c1e[1] + c1o[1];
            sg[0][r0 + 24] = c1e[2] + c1o[2];  sg[1][r0 + 24] = c1e[3] + c1o[3];
        }
        __syncthreads();

        if (tid < 256) {
            float gi = sg[cn][ci]       + __half2float(xn0);
            float gf = sg[cn][128 + ci] + __half2float(xn1);
            float gg = sg[cn][256 + ci] + __half2float(xn2);
            float go = sg[cn][384 + ci] + __half2float(xn3);
            if (s + 1 < T_) {
                const __half* p = g_xwh + xwrow0 + (long)(t + dt) * G4_;
                xn0 = p[ci]; xn1 = p[128 + ci];
                xn2 = p[256 + ci]; xn3 = p[384 + ci];
            }
            gi = sigmoid_hw(gi);
            gf = sigmoid_hw(gf);
            gg = tanh_hw(gg);
            go = sigmoid_hw(go);
            float ccs = fmaf(gf, cst, gi * gg);
            cst = ccs;
            float hv = go * tanh_hw(ccs);
            hout[(long)t * (2 * H_)] = hv;
            sh16[cn][ci] = __float2half(hv);
        }
        __syncthreads();
    }
}

// ==========================================================================
// Kernel 3: logits + CRF emission precompute (unchanged).
// ==========================================================================
__global__ void __launch_bounds__(256) k_logits(
    const float* __restrict__ fcW, const float* __restrict__ fcb,
    float* __restrict__ logits)
{
    __shared__ float sW[20 * 257];
    __shared__ float shh[16 * 257];
    __shared__ float sl[16 * 20];
    const int tid = threadIdx.x;
    const long bt0 = (long)blockIdx.x * 16;

    for (int i = tid; i < 20 * 256; i += 256) {
        int cc = i >> 8, k = i & 255;
        sW[cc * 257 + k] = fcW[i];
    }
    for (int i = tid; i < 16 * 256; i += 256) {
        int tk = i >> 8, k = i & 255;
        shh[tk * 257 + k] = g_h[(bt0 + tk) * 256 + k];
    }
    __syncthreads();
    for (int o = tid; o < 16 * 20; o += 256) {
        int tk = o / 20, cc = o % 20;
        const float* hr = shh + tk * 257;
        const float* wr = sW  + cc * 257;
        float a0 = 0.f, a1 = 0.f, a2 = 0.f, a3 = 0.f;
#pragma unroll 16
        for (int k = 0; k < 256; k += 4) {
            a0 = fmaf(hr[k + 0], wr[k + 0], a0);
            a1 = fmaf(hr[k + 1], wr[k + 1], a1);
            a2 = fmaf(hr[k + 2], wr[k + 2], a2);
            a3 = fmaf(hr[k + 3], wr[k + 3], a3);
        }
        float lv = fcb[cc] + ((a0 + a1) + (a2 + a3));
        sl[o] = lv;
        logits[(bt0 + tk) * C_ + cc] = lv;
    }
    __syncthreads();
    for (int o = tid; o < 16 * 20; o += 256) {
        int tk = o / 20, cc = o % 20;
        g_eexp[(bt0 + tk) * C_ + cc] = __expf(sl[o] - sl[tk * 20]);
        if (cc == 0) g_em0[bt0 + tk] = sl[tk * 20];
    }
}

// ==========================================================================
// Kernel 4: CRF — exp-space scan from SMEM-resident tables (unchanged).
// ==========================================================================
__global__ void __launch_bounds__(128) k_crf(
    const float* __restrict__ logits,
    const int*   __restrict__ tags,
    const void*  __restrict__ maskp,
    const float* __restrict__ trans)
{
    __shared__ __align__(16) float sEE[T_ * C_];
    __shared__ __align__(16) float sEM0[T_];
    __shared__ float sT[400];
    __shared__ float sPart[8];
    const int tid  = threadIdx.x;
    const int lane = tid & 31;
    const int wid  = tid >> 5;
    const int b    = blockIdx.x;
    const int isbyte = (((const int*)maskp)[0] == 0x01010101);
    const long mbase = (long)b * T_;

    {
        const float4* src = (const float4*)(g_eexp + mbase * C_);
        float4* dst = (float4*)sEE;
        for (int i = tid; i < (T_ * C_) / 4; i += 128) dst[i] = src[i];
        const float4* s2 = (const float4*)(g_em0 + mbase);
        float4* d2 = (float4*)sEM0;
        for (int i = tid; i < T_ / 4; i += 128) d2[i] = s2[i];
    }
    for (int i = tid; i < 400; i += 128) sT[i] = trans[i];

    int lcnt = 0;
    for (int t = tid; t < T_; t += 128)
        lcnt += (load_mask(maskp, mbase + t, isbyte) != 0);
    for (int o = 16; o; o >>= 1) lcnt += __shfl_xor_sync(0xffffffffu, lcnt, o);
    if (lane == 0) sPart[4 + wid] = (float)lcnt;
    __syncthreads();
    const int len = (int)(sPart[4] + sPart[5] + sPart[6] + sPart[7]);

    const float* lg = logits + mbase * C_;

    if (wid == 0) {
        float Ecol[20];
#pragma unroll
        for (int i = 0; i < 20; i++)
            Ecol[i] = (lane < 20) ? __expf(sT[i * 20 + lane]) : 0.0f;

        float u = (lane < 20) ? sEE[lane] : 0.0f;
        float L = sEM0[0];

        for (int t = 1; t < len; t++) {
            float eeC  = (lane < 20) ? sEE[t * C_ + lane] : 0.0f;
            float em0C = sEM0[t];
            float s0 = 0.f, s1 = 0.f, s2 = 0.f, s3 = 0.f;
#pragma unroll
            for (int i = 0; i < 20; i += 4) {
                s0 = fmaf(__shfl_sync(0xffffffffu, u, i + 0), Ecol[i + 0], s0);
                s1 = fmaf(__shfl_sync(0xffffffffu, u, i + 1), Ecol[i + 1], s1);
                s2 = fmaf(__shfl_sync(0xffffffffu, u, i + 2), Ecol[i + 2], s2);
                s3 = fmaf(__shfl_sync(0xffffffffu, u, i + 3), Ecol[i + 3], s3);
            }
            u = eeC * ((s0 + s1) + (s2 + s3));
            L += em0C;
            if ((t & 3) == 0) {
                float k = __shfl_sync(0xffffffffu, u, 0);
                u *= __fdividef(1.0f, k);
                L += __logf(k);
            }
        }
        float e = u;
        for (int o = 16; o; o >>= 1) e += __shfl_xor_sync(0xffffffffu, e, o);
        if (lane == 0) sPart[0] = L + __logf(e);
    } else {
        const int id = tid - 32;
        float sn = 0.0f;
        for (int t = id; t < len; t += 96)
            sn += lg[t * C_ + tags[mbase + t]];
        for (int t = id; t < len - 1; t += 96)
            sn += sT[tags[mbase + t] * 20 + tags[mbase + t + 1]];
        for (int o = 16; o; o >>= 1) sn += __shfl_xor_sync(0xffffffffu, sn, o);
        if (lane == 0) sPart[wid] = sn;
    }
    __syncthreads();
    if (tid == 0)
        g_res[b] = sPart[0] - (sPart[1] + sPart[2] + sPart[3]);
}

// Kernel 5: deterministic mean over batches -> loss
__global__ void k_final(float* __restrict__ out)
{
    const int lane = threadIdx.x;
    float v = g_res[lane] + g_res[lane + 32];
    for (int o = 16; o; o >>= 1) v += __shfl_xor_sync(0xffffffffu, v, o);
    if (lane == 0) out[0] = v * (1.0f / 64.0f);
}

// ==========================================================================
extern "C" void kernel_launch(void* const* d_in, const int* in_sizes, int n_in,
                              void* d_out, int out_size)
{
    const int*   x      = (const int*)  d_in[0];
    const void*  mask   =               d_in[1];
    const int*   tags   = (const int*)  d_in[2];
    const float* emb    = (const float*)d_in[3];
    const float* W_ih_f = (const float*)d_in[4];
    const float* W_hh_f = (const float*)d_in[5];
    const float* b_ih_f = (const float*)d_in[6];
    const float* b_hh_f = (const float*)d_in[7];
    const float* W_ih_b = (const float*)d_in[8];
    const float* W_hh_b = (const float*)d_in[9];
    const float* b_ih_b = (const float*)d_in[10];
    const float* b_hh_b = (const float*)d_in[11];
    const float* fc_W   = (const float*)d_in[12];
    const float* fc_b   = (const float*)d_in[13];
    const float* trans  = (const float*)d_in[14];

    float* out        = (float*)d_out;
    float* loss_ptr   = out;
    float* logits_ptr = out + 1;
    if (out_size == BT_ * C_) {
        logits_ptr = out;
        loss_ptr   = nullptr;
    }

    const int gemm_smem = 2 * 3 * 5120 * 2;             // 61440 B
    cudaFuncSetAttribute(k_input_gemm,
                         cudaFuncAttributeMaxDynamicSharedMemorySize, gemm_smem);

    {
        long ntot = (long)BT_ * (KP_ / 2) + (long)2 * G4_ * (KP_ / 2);
        int nblk = (int)((ntot + 255) / 256);
        k_cvt<<<nblk, 256>>>(x, emb, W_ih_f, W_ih_b);
        k_bias<<<(2 * G4_ + 255) / 256, 256>>>(b_ih_f, b_hh_f, b_ih_b, b_hh_b);
    }
    k_input_gemm<<<dim3(8, 256), 256, gemm_smem>>>();
    k_lstm<<<64, 512>>>(W_hh_f, W_hh_b);
    k_logits<<<BT_ / 16, 256>>>(fc_W, fc_b, logits_ptr);
    k_crf<<<B_, 128>>>(logits_ptr, tags, mask, trans);
    if (loss_ptr) k_final<<<1, 32>>>(loss_ptr);
}